// round 3
// baseline (speedup 1.0000x reference)
#include <cuda_runtime.h>

// DeformationGrid: trilinear interpolation of a (160,160,160,3) f32 grid at
// 4,194,304 random points in the unit cube.
//
// Strategy:
//   1) repack_kernel: theta (3 floats/voxel, 12B stride -> unvectorizable) into
//      a padded float4-per-voxel __device__ scratch array (65.5 MB, fits L2).
//   2) trilerp_kernel: 8x LDG.E.128 gathers per point + FMA blend.
//      Streaming data (coords in, out) uses evict-first hints (__ldcs/__stcs)
//      to avoid thrashing the grid out of L2.

static constexpr int NX = 160, NY = 160, NZ = 160;
static constexpr int NVOX = NX * NY * NZ;

// Scratch: padded grid, float4 per voxel (w unused). 65,536,000 bytes.
__device__ float4 g_grid[NVOX];

__global__ void __launch_bounds__(256)
repack_kernel(const float* __restrict__ theta) {
    int v = blockIdx.x * blockDim.x + threadIdx.x;
    if (v >= NVOX) return;
    const float* p = theta + 3 * v;
    // Coalesced streaming read of the 12B/voxel source.
    float a = __ldcs(p + 0);
    float b = __ldcs(p + 1);
    float c = __ldcs(p + 2);
    g_grid[v] = make_float4(a, b, c, 0.0f);
}

__global__ void __launch_bounds__(256)
trilerp_kernel(const float* __restrict__ coords,
               float* __restrict__ out,
               int n) {
    int i = blockIdx.x * blockDim.x + threadIdx.x;
    if (i >= n) return;

    // Streaming coalesced reads (evict-first: don't pollute L2, grid lives there).
    float cx = __ldcs(coords + 3 * i + 0);
    float cy = __ldcs(coords + 3 * i + 1);
    float cz = __ldcs(coords + 3 * i + 2);

    // Voxel-space coordinates (scale = dim - 1, per reference).
    float px = cx * (float)(NX - 1);
    float py = cy * (float)(NY - 1);
    float pz = cz * (float)(NZ - 1);
    float fx = floorf(px), fy = floorf(py), fz = floorf(pz);
    float tx = px - fx, ty = py - fy, tz = pz - fz;
    int ix = (int)fx, iy = (int)fy, iz = (int)fz;

    // Per-axis corner validity (reference: cval=0 outside). Folding validity
    // into the per-axis weight is exact: the corner weight is the product of
    // axis weights, and corner validity is the conjunction of axis validities.
    bool vx0 = (ix >= 0) && (ix < NX);
    bool vx1 = (ix + 1 >= 0) && (ix + 1 < NX);
    bool vy0 = (iy >= 0) && (iy < NY);
    bool vy1 = (iy + 1 >= 0) && (iy + 1 < NY);
    bool vz0 = (iz >= 0) && (iz < NZ);
    bool vz1 = (iz + 1 >= 0) && (iz + 1 < NZ);

    float wx0 = vx0 ? (1.0f - tx) : 0.0f;
    float wx1 = vx1 ? tx : 0.0f;
    float wy0 = vy0 ? (1.0f - ty) : 0.0f;
    float wy1 = vy1 ? ty : 0.0f;
    float wz0 = vz0 ? (1.0f - tz) : 0.0f;
    float wz1 = vz1 ? tz : 0.0f;

    // Clamped indices (reference clips, then zeroes via the weight).
    int ix0 = min(max(ix, 0), NX - 1);
    int ix1 = min(max(ix + 1, 0), NX - 1);
    int iy0 = min(max(iy, 0), NY - 1);
    int iy1 = min(max(iy + 1, 0), NY - 1);
    int iz0 = min(max(iz, 0), NZ - 1);
    int iz1 = min(max(iz + 1, 0), NZ - 1);

    int a00 = (ix0 * NY + iy0) * NZ;
    int a01 = (ix0 * NY + iy1) * NZ;
    int a10 = (ix1 * NY + iy0) * NZ;
    int a11 = (ix1 * NY + iy1) * NZ;

    // 8 independent 16B gathers -> high MLP, compiler front-batches them.
    float4 c000 = __ldg(&g_grid[a00 + iz0]);
    float4 c001 = __ldg(&g_grid[a00 + iz1]);
    float4 c010 = __ldg(&g_grid[a01 + iz0]);
    float4 c011 = __ldg(&g_grid[a01 + iz1]);
    float4 c100 = __ldg(&g_grid[a10 + iz0]);
    float4 c101 = __ldg(&g_grid[a10 + iz1]);
    float4 c110 = __ldg(&g_grid[a11 + iz0]);
    float4 c111 = __ldg(&g_grid[a11 + iz1]);

    float w000 = wx0 * wy0 * wz0;
    float w001 = wx0 * wy0 * wz1;
    float w010 = wx0 * wy1 * wz0;
    float w011 = wx0 * wy1 * wz1;
    float w100 = wx1 * wy0 * wz0;
    float w101 = wx1 * wy0 * wz1;
    float w110 = wx1 * wy1 * wz0;
    float w111 = wx1 * wy1 * wz1;

    float ox = 0.0f, oy = 0.0f, oz = 0.0f;
    ox = fmaf(w000, c000.x, ox); oy = fmaf(w000, c000.y, oy); oz = fmaf(w000, c000.z, oz);
    ox = fmaf(w001, c001.x, ox); oy = fmaf(w001, c001.y, oy); oz = fmaf(w001, c001.z, oz);
    ox = fmaf(w010, c010.x, ox); oy = fmaf(w010, c010.y, oy); oz = fmaf(w010, c010.z, oz);
    ox = fmaf(w011, c011.x, ox); oy = fmaf(w011, c011.y, oy); oz = fmaf(w011, c011.z, oz);
    ox = fmaf(w100, c100.x, ox); oy = fmaf(w100, c100.y, oy); oz = fmaf(w100, c100.z, oz);
    ox = fmaf(w101, c101.x, ox); oy = fmaf(w101, c101.y, oy); oz = fmaf(w101, c101.z, oz);
    ox = fmaf(w110, c110.x, ox); oy = fmaf(w110, c110.y, oy); oz = fmaf(w110, c110.z, oz);
    ox = fmaf(w111, c111.x, ox); oy = fmaf(w111, c111.y, oy); oz = fmaf(w111, c111.z, oz);

    // Coalesced streaming writes (evict-first).
    __stcs(out + 3 * i + 0, ox);
    __stcs(out + 3 * i + 1, oy);
    __stcs(out + 3 * i + 2, oz);
}

extern "C" void kernel_launch(void* const* d_in, const int* in_sizes, int n_in,
                              void* d_out, int out_size) {
    const float* coords = (const float*)d_in[0];   // (N_POINTS, 3) f32
    const float* theta  = (const float*)d_in[1];   // (160,160,160,3) f32
    float* out = (float*)d_out;                    // (N_POINTS, 3) f32

    int n = in_sizes[0] / 3;

    repack_kernel<<<(NVOX + 255) / 256, 256>>>(theta);
    trilerp_kernel<<<(n + 255) / 256, 256>>>(coords, out, n);
}

// round 4
// speedup vs baseline: 1.3361x; 1.3361x over previous
#include <cuda_runtime.h>
#include <cuda_fp16.h>

// DeformationGrid: trilinear interpolation of a (160,160,160,3) f32 grid at
// 4,194,304 random points in the unit cube.
//
// R3: the trilerp kernel is L1tex-WAVEFRONT bound (8 divergent 16B gathers per
// point -> ~32 wavefronts/instr/warp). Halve the gather instruction count by
// repacking the grid into a redundant fp16 z-pair layout:
//   entry[x][y][z] (16B) = { v(z).xyz as f16, pad, v(z+1).xyz as f16, pad }
// so ONE aligned LDG.E.128 fetches BOTH z-adjacent corners -> 4 gathers/point.
// Weights remain exact f32; only corner values are fp16-rounded (~1e-4 rel,
// threshold is 1e-3).

static constexpr int NX = 160, NY = 160, NZ = 160;
static constexpr int NVOX = NX * NY * NZ;

// 16B per entry, 65,536,000 bytes total — fits in the 126 MB L2.
__device__ uint4 g_grid[NVOX];

__device__ __forceinline__ unsigned pack2(float a, float b) {
    __half2 h = __floats2half2_rn(a, b);
    return *reinterpret_cast<unsigned*>(&h);
}

__global__ void __launch_bounds__(256)
repack_kernel(const float* __restrict__ theta) {
    int v = blockIdx.x * blockDim.x + threadIdx.x;
    if (v >= NVOX) return;
    int z = v % NZ;
    const float* p = theta + 3 * v;
    float a0 = __ldcs(p + 0);
    float a1 = __ldcs(p + 1);
    float a2 = __ldcs(p + 2);
    float b0 = 0.0f, b1 = 0.0f, b2 = 0.0f;
    if (z + 1 < NZ) {            // z-pair partner (zeros at the z edge;
        b0 = __ldcs(p + 3);      //  its weight is provably 0 there)
        b1 = __ldcs(p + 4);
        b2 = __ldcs(p + 5);
    }
    uint4 e;
    e.x = pack2(a0, a1);
    e.y = pack2(a2, 0.0f);
    e.z = pack2(b0, b1);
    e.w = pack2(b2, 0.0f);
    g_grid[v] = e;
}

// Unpack one 16B entry and accumulate both z corners with weights (w0, w1).
__device__ __forceinline__ void accum_pair(uint4 e, float w0, float w1,
                                           float& ox, float& oy, float& oz) {
    float2 v01 = __half22float2(*reinterpret_cast<__half2*>(&e.x));
    float  v2  = __half2float(*reinterpret_cast<__half*>(&e.y));
    float2 u01 = __half22float2(*reinterpret_cast<__half2*>(&e.z));
    float  u2  = __half2float(*reinterpret_cast<__half*>(&e.w));
    ox = fmaf(w0, v01.x, ox); oy = fmaf(w0, v01.y, oy); oz = fmaf(w0, v2, oz);
    ox = fmaf(w1, u01.x, ox); oy = fmaf(w1, u01.y, oy); oz = fmaf(w1, u2, oz);
}

__global__ void __launch_bounds__(256)
trilerp_kernel(const float* __restrict__ coords,
               float* __restrict__ out,
               int n) {
    int i = blockIdx.x * blockDim.x + threadIdx.x;
    if (i >= n) return;

    // Streaming coalesced reads (evict-first: keep L2 for the grid).
    float cx = __ldcs(coords + 3 * i + 0);
    float cy = __ldcs(coords + 3 * i + 1);
    float cz = __ldcs(coords + 3 * i + 2);

    float px = cx * (float)(NX - 1);
    float py = cy * (float)(NY - 1);
    float pz = cz * (float)(NZ - 1);
    float fx = floorf(px), fy = floorf(py), fz = floorf(pz);
    float tx = px - fx, ty = py - fy, tz = pz - fz;
    int ix = (int)fx, iy = (int)fy, iz = (int)fz;

    // Per-axis validity folded into axis weights (cval=0 outside).
    bool vx0 = (ix >= 0) && (ix < NX);
    bool vx1 = (ix + 1 >= 0) && (ix + 1 < NX);
    bool vy0 = (iy >= 0) && (iy < NY);
    bool vy1 = (iy + 1 >= 0) && (iy + 1 < NY);
    bool vz0 = (iz >= 0) && (iz < NZ);
    bool vz1 = (iz + 1 >= 0) && (iz + 1 < NZ);

    float wx0 = vx0 ? (1.0f - tx) : 0.0f;
    float wx1 = vx1 ? tx : 0.0f;
    float wy0 = vy0 ? (1.0f - ty) : 0.0f;
    float wy1 = vy1 ? ty : 0.0f;
    float wz0 = vz0 ? (1.0f - tz) : 0.0f;
    float wz1 = vz1 ? tz : 0.0f;

    int ix0 = min(max(ix, 0), NX - 1);
    int ix1 = min(max(ix + 1, 0), NX - 1);
    int iy0 = min(max(iy, 0), NY - 1);
    int iy1 = min(max(iy + 1, 0), NY - 1);
    int iz0 = min(max(iz, 0), NZ - 1);   // pair entry covers (iz0, iz0+1)

    int a00 = (ix0 * NY + iy0) * NZ + iz0;
    int a01 = (ix0 * NY + iy1) * NZ + iz0;
    int a10 = (ix1 * NY + iy0) * NZ + iz0;
    int a11 = (ix1 * NY + iy1) * NZ + iz0;

    // 4 independent 16B gathers, each yielding BOTH z corners.
    uint4 e00 = __ldg(&g_grid[a00]);
    uint4 e01 = __ldg(&g_grid[a01]);
    uint4 e10 = __ldg(&g_grid[a10]);
    uint4 e11 = __ldg(&g_grid[a11]);

    float w00 = wx0 * wy0;
    float w01 = wx0 * wy1;
    float w10 = wx1 * wy0;
    float w11 = wx1 * wy1;

    float ox = 0.0f, oy = 0.0f, oz = 0.0f;
    accum_pair(e00, w00 * wz0, w00 * wz1, ox, oy, oz);
    accum_pair(e01, w01 * wz0, w01 * wz1, ox, oy, oz);
    accum_pair(e10, w10 * wz0, w10 * wz1, ox, oy, oz);
    accum_pair(e11, w11 * wz0, w11 * wz1, ox, oy, oz);

    __stcs(out + 3 * i + 0, ox);
    __stcs(out + 3 * i + 1, oy);
    __stcs(out + 3 * i + 2, oz);
}

extern "C" void kernel_launch(void* const* d_in, const int* in_sizes, int n_in,
                              void* d_out, int out_size) {
    const float* coords = (const float*)d_in[0];   // (N_POINTS, 3) f32
    const float* theta  = (const float*)d_in[1];   // (160,160,160,3) f32
    float* out = (float*)d_out;                    // (N_POINTS, 3) f32

    int n = in_sizes[0] / 3;

    repack_kernel<<<(NVOX + 255) / 256, 256>>>(theta);
    trilerp_kernel<<<(n + 255) / 256, 256>>>(coords, out, n);
}

// round 5
// speedup vs baseline: 1.4065x; 1.0527x over previous
#include <cuda_runtime.h>
#include <cuda_fp16.h>

// DeformationGrid: trilinear interpolation of a (160,160,160,3) f32 grid at
// 4,194,304 random points.
//
// R4: lane-pair gather merging. Grid layout is y-FASTEST:
//   entry[(x*NZ + z)*NY + y] = 16B fp16 z-pair {v(z).xyz, v(z+1).xyz}
// A point's two y-neighbor entries are 16B apart -> same 128B line (7/8 of
// the time). Each point is handled by a LANE PAIR: lane 2j takes row iy,
// lane 2j+1 takes row iy+1, so one LDG.E.128 instruction fetches BOTH y rows
// and they coalesce into ONE L1 wavefront. 2.25 wavefronts/point (was 4),
// ~3 L2 sectors/point (was 4). Pair partials combine via shfl_xor.

static constexpr int NX = 160, NY = 160, NZ = 160;
static constexpr int NVOX = NX * NY * NZ;

// 16B per entry, 65,536,000 bytes — L2-resident (126 MB L2).
__device__ uint4 g_grid[NVOX];

__device__ __forceinline__ unsigned pack2(float a, float b) {
    __half2 h = __floats2half2_rn(a, b);
    return *reinterpret_cast<unsigned*>(&h);
}
__device__ __forceinline__ float2 unpk2(unsigned u) {
    __half2 h = *reinterpret_cast<__half2*>(&u);
    return __half22float2(h);
}

// ---------------------------------------------------------------------------
// Repack: theta (x,y,z,c) f32 -> g_grid[(x*NZ+z)*NY+y] fp16 z-pair entries.
// 32(y) x 32(z) tile per block, staged in SMEM so both the coalesced read
// (z-contiguous) and the permuted write (y-contiguous) stay coalesced.
// ---------------------------------------------------------------------------
static constexpr int TY = 32, TZ = 32;
static constexpr int ROWF = (TZ + 1) * 3;   // 99 floats per y-row (z halo +1)

__global__ void __launch_bounds__(256)
repack_kernel(const float* __restrict__ theta) {
    __shared__ float s[TY][ROWF];   // 12.7 KB; stride 99 (odd*3) -> conflict-free

    int b = blockIdx.x;
    int tzi = b % (NZ / TZ);
    int tyi = (b / (NZ / TZ)) % (NY / TY);
    int x   = b / ((NZ / TZ) * (NY / TY));
    int y0 = tyi * TY;
    int z0 = tzi * TZ;

    // Load: 32 y-rows of 99 contiguous floats each (z-major source).
    const int row_base_limit = NZ * 3;          // valid float offset within a row
    for (int t = threadIdx.x; t < TY * ROWF; t += 256) {
        int y = t / ROWF;
        int rem = t % ROWF;                     // z*3 + c within the tile (+halo)
        int zf = z0 * 3 + rem;
        float v = 0.0f;
        if (zf < row_base_limit) {              // z halo beyond NZ -> 0 (weight is 0 there)
            v = __ldcs(theta + (size_t)((x * NY + y0 + y) * NZ) * 3 + zf);
        }
        s[y][rem] = v;
    }
    __syncthreads();

    // Write: y-fastest entry order -> coalesced 16B stores.
    for (int e = threadIdx.x; e < TY * TZ; e += 256) {
        int y = e % TY;
        int z = e / TY;
        float a0 = s[y][z * 3 + 0];
        float a1 = s[y][z * 3 + 1];
        float a2 = s[y][z * 3 + 2];
        float b0 = s[y][z * 3 + 3];
        float b1 = s[y][z * 3 + 4];
        float b2 = s[y][z * 3 + 5];
        uint4 E;
        E.x = pack2(a0, a1);
        E.y = pack2(a2, 0.0f);
        E.z = pack2(b0, b1);
        E.w = pack2(b2, 0.0f);
        g_grid[(x * NZ + (z0 + z)) * NY + (y0 + y)] = E;
    }
}

// ---------------------------------------------------------------------------
// Trilerp: 2 threads per point. Lane 2j handles y-row iy, lane 2j+1 handles
// y-row iy+1. Two LDG.E.128 per lane (x0 entry, x1 entry); the lane pair's
// addresses in each instruction are 16B apart -> one merged wavefront.
// ---------------------------------------------------------------------------
__global__ void __launch_bounds__(256)
trilerp_kernel(const float* __restrict__ coords,
               float* __restrict__ out,
               int n) {
    int gid = blockIdx.x * blockDim.x + threadIdx.x;
    int p = gid >> 1;        // point index
    int r = gid & 1;         // y-role within the lane pair
    if (p >= n) return;

    float cx = __ldcs(coords + 3 * p + 0);
    float cy = __ldcs(coords + 3 * p + 1);
    float cz = __ldcs(coords + 3 * p + 2);

    float px = cx * (float)(NX - 1);
    float py = cy * (float)(NY - 1);
    float pz = cz * (float)(NZ - 1);
    float fx = floorf(px), fy = floorf(py), fz = floorf(pz);
    float tx = px - fx, ty = py - fy, tz = pz - fz;
    int ix = (int)fx, iy = (int)fy, iz = (int)fz;

    // Per-axis validity folded into axis weights (reference: cval=0 outside).
    bool vx0 = (ix >= 0) && (ix < NX);
    bool vx1 = (ix + 1 >= 0) && (ix + 1 < NX);
    bool vy0 = (iy >= 0) && (iy < NY);
    bool vy1 = (iy + 1 >= 0) && (iy + 1 < NY);
    bool vz0 = (iz >= 0) && (iz < NZ);
    bool vz1 = (iz + 1 >= 0) && (iz + 1 < NZ);

    float wx0 = vx0 ? (1.0f - tx) : 0.0f;
    float wx1 = vx1 ? tx : 0.0f;
    float wy0 = vy0 ? (1.0f - ty) : 0.0f;
    float wy1 = vy1 ? ty : 0.0f;
    float wz0 = vz0 ? (1.0f - tz) : 0.0f;
    float wz1 = vz1 ? tz : 0.0f;

    int ix0 = min(max(ix, 0), NX - 1);
    int ix1 = min(max(ix + 1, 0), NX - 1);
    int iy0 = min(max(iy, 0), NY - 1);
    int iz0 = min(max(iz, 0), NZ - 1);

    int yr = min(iy0 + r, NY - 1);       // this lane's y row
    float wyr = r ? wy1 : wy0;

    int e0 = (ix0 * NZ + iz0) * NY + yr;
    int e1 = (ix1 * NZ + iz0) * NY + yr;

    // Lane pair addresses are 16B apart within each instruction -> merged wf.
    uint4 A = __ldg(&g_grid[e0]);        // x0 entry: z-pair at (x0, yr)
    uint4 B = __ldg(&g_grid[e1]);        // x1 entry: z-pair at (x1, yr)

    float2 Az0 = unpk2(A.x);  float Az0z = unpk2(A.y).x;
    float2 Az1 = unpk2(A.z);  float Az1z = unpk2(A.w).x;
    float2 Bz0 = unpk2(B.x);  float Bz0z = unpk2(B.y).x;
    float2 Bz1 = unpk2(B.z);  float Bz1z = unpk2(B.w).x;

    // z-interp, then x-interp, scaled by this lane's y weight.
    float sx = wyr * (wx0 * fmaf(wz0, Az0.x, wz1 * Az1.x) +
                      wx1 * fmaf(wz0, Bz0.x, wz1 * Bz1.x));
    float sy = wyr * (wx0 * fmaf(wz0, Az0.y, wz1 * Az1.y) +
                      wx1 * fmaf(wz0, Bz0.y, wz1 * Bz1.y));
    float sz = wyr * (wx0 * fmaf(wz0, Az0z, wz1 * Az1z) +
                      wx1 * fmaf(wz0, Bz0z, wz1 * Bz1z));

    // Combine the two y rows across the lane pair.
    unsigned mask = __activemask();
    sx += __shfl_xor_sync(mask, sx, 1);
    sy += __shfl_xor_sync(mask, sy, 1);
    sz += __shfl_xor_sync(mask, sz, 1);

    if (r == 0) {
        __stcs(out + 3 * p + 0, sx);
        __stcs(out + 3 * p + 1, sy);
        __stcs(out + 3 * p + 2, sz);
    }
}

extern "C" void kernel_launch(void* const* d_in, const int* in_sizes, int n_in,
                              void* d_out, int out_size) {
    const float* coords = (const float*)d_in[0];   // (N_POINTS, 3) f32
    const float* theta  = (const float*)d_in[1];   // (160,160,160,3) f32
    float* out = (float*)d_out;                    // (N_POINTS, 3) f32

    int n = in_sizes[0] / 3;

    int repack_blocks = NX * (NY / TY) * (NZ / TZ);   // 160*5*5 = 4000
    repack_kernel<<<repack_blocks, 256>>>(theta);

    long long threads = 2LL * n;
    int blocks = (int)((threads + 255) / 256);
    trilerp_kernel<<<blocks, 256>>>(coords, out, n);
}

// round 8
// speedup vs baseline: 1.5566x; 1.1067x over previous
#include <cuda_runtime.h>
#include <cuda_fp16.h>

// DeformationGrid: trilinear interpolation of a (160,160,160,3) f32 grid at
// 4,194,304 random points.
//
// R5: trilerp unchanged (lane-pair gather merging, 2.25 L1 wavefronts/point).
// Repack rebuilt: per-block slab = (1 x, 20 y, full z) whose SOURCE region is
// fully contiguous (38.4 KB) -> pure float4 streaming loads into SMEM, then
// coalesced y-fastest fp16 z-pair entry writes. Full z in-tile kills the halo.

static constexpr int NX = 160, NY = 160, NZ = 160;
static constexpr int NVOX = NX * NY * NZ;

// 16B per entry, y-fastest: g_grid[(x*NZ + z)*NY + y]. 65,536,000 bytes.
__device__ uint4 g_grid[NVOX];

__device__ __forceinline__ unsigned pack2(float a, float b) {
    __half2 h = __floats2half2_rn(a, b);
    return *reinterpret_cast<unsigned*>(&h);
}
__device__ __forceinline__ float2 unpk2(unsigned u) {
    __half2 h = *reinterpret_cast<__half2*>(&u);
    return __half22float2(h);
}

// ---------------------------------------------------------------------------
// Repack: theta (x,y,z,c) f32 -> g_grid[(x*NZ+z)*NY+y] fp16 z-pair entries.
// ---------------------------------------------------------------------------
static constexpr int TY = 20;                // y-rows per block
static constexpr int ROWF = NZ * 3;          // 480 floats per y-row
static constexpr int SROW = ROWF + 3;        // 483: mod 32 = 3 -> conflict-free

__global__ void __launch_bounds__(256)
repack_kernel(const float* __restrict__ theta) {
    __shared__ float s[TY * SROW];           // 38,640 B

    int b = blockIdx.x;
    int tyi = b % (NY / TY);                 // 8 y-tiles
    int x   = b / (NY / TY);
    int y0 = tyi * TY;

    // Load: the (x, y0..y0+TY-1, all z, all c) region is one contiguous
    // 20*480-float block. Stream it in with float4 (base is 1920B-aligned).
    const float4* src = reinterpret_cast<const float4*>(
        theta + (size_t)(x * NY + y0) * ROWF);
    for (int t = threadIdx.x; t < TY * ROWF / 4; t += 256) {
        float4 v = __ldcs(src + t);
        int off = t * 4;                     // never crosses a 480-float row
        int row = off / ROWF;
        int col = off - row * ROWF;
        float* d = s + row * SROW + col;
        d[0] = v.x; d[1] = v.y; d[2] = v.z; d[3] = v.w;
    }
    __syncthreads();

    // Write: y-fastest entries, coalesced 16B stores.
    for (int e = threadIdx.x; e < NZ * TY; e += 256) {
        int y = e % TY;
        int z = e / TY;
        const float* r = s + y * SROW + z * 3;
        float a0 = r[0], a1 = r[1], a2 = r[2];
        bool in = (z + 1 < NZ);              // z-edge partner weight is 0
        float b0 = in ? r[3] : 0.0f;
        float b1 = in ? r[4] : 0.0f;
        float b2 = in ? r[5] : 0.0f;
        uint4 E;
        E.x = pack2(a0, a1);
        E.y = pack2(a2, 0.0f);
        E.z = pack2(b0, b1);
        E.w = pack2(b2, 0.0f);
        g_grid[(x * NZ + z) * NY + (y0 + y)] = E;
    }
}

// ---------------------------------------------------------------------------
// Trilerp: 2 threads per point. Lane 2j handles y-row iy, lane 2j+1 handles
// y-row iy+1. Two LDG.E.128 per lane (x0 entry, x1 entry); the lane pair's
// addresses in each instruction are 16B apart -> one merged wavefront.
// ---------------------------------------------------------------------------
__global__ void __launch_bounds__(256)
trilerp_kernel(const float* __restrict__ coords,
               float* __restrict__ out,
               int n) {
    int gid = blockIdx.x * blockDim.x + threadIdx.x;
    int p = gid >> 1;        // point index
    int r = gid & 1;         // y-role within the lane pair
    if (p >= n) return;

    float cx = __ldcs(coords + 3 * p + 0);
    float cy = __ldcs(coords + 3 * p + 1);
    float cz = __ldcs(coords + 3 * p + 2);

    float px = cx * (float)(NX - 1);
    float py = cy * (float)(NY - 1);
    float pz = cz * (float)(NZ - 1);
    float fx = floorf(px), fy = floorf(py), fz = floorf(pz);
    float tx = px - fx, ty = py - fy, tz = pz - fz;
    int ix = (int)fx, iy = (int)fy, iz = (int)fz;

    // Per-axis validity folded into axis weights (reference: cval=0 outside).
    bool vx0 = (ix >= 0) && (ix < NX);
    bool vx1 = (ix + 1 >= 0) && (ix + 1 < NX);
    bool vy0 = (iy >= 0) && (iy < NY);
    bool vy1 = (iy + 1 >= 0) && (iy + 1 < NY);
    bool vz0 = (iz >= 0) && (iz < NZ);
    bool vz1 = (iz + 1 >= 0) && (iz + 1 < NZ);

    float wx0 = vx0 ? (1.0f - tx) : 0.0f;
    float wx1 = vx1 ? tx : 0.0f;
    float wy0 = vy0 ? (1.0f - ty) : 0.0f;
    float wy1 = vy1 ? ty : 0.0f;
    float wz0 = vz0 ? (1.0f - tz) : 0.0f;
    float wz1 = vz1 ? tz : 0.0f;

    int ix0 = min(max(ix, 0), NX - 1);
    int ix1 = min(max(ix + 1, 0), NX - 1);
    int iy0 = min(max(iy, 0), NY - 1);
    int iz0 = min(max(iz, 0), NZ - 1);

    int yr = min(iy0 + r, NY - 1);       // this lane's y row
    float wyr = r ? wy1 : wy0;

    int e0 = (ix0 * NZ + iz0) * NY + yr;
    int e1 = (ix1 * NZ + iz0) * NY + yr;

    // Lane pair addresses are 16B apart within each instruction -> merged wf.
    uint4 A = __ldg(&g_grid[e0]);        // x0 entry: z-pair at (x0, yr)
    uint4 B = __ldg(&g_grid[e1]);        // x1 entry: z-pair at (x1, yr)

    float2 Az0 = unpk2(A.x);  float Az0z = unpk2(A.y).x;
    float2 Az1 = unpk2(A.z);  float Az1z = unpk2(A.w).x;
    float2 Bz0 = unpk2(B.x);  float Bz0z = unpk2(B.y).x;
    float2 Bz1 = unpk2(B.z);  float Bz1z = unpk2(B.w).x;

    // z-interp, then x-interp, scaled by this lane's y weight.
    float sx = wyr * (wx0 * fmaf(wz0, Az0.x, wz1 * Az1.x) +
                      wx1 * fmaf(wz0, Bz0.x, wz1 * Bz1.x));
    float sy = wyr * (wx0 * fmaf(wz0, Az0.y, wz1 * Az1.y) +
                      wx1 * fmaf(wz0, Bz0.y, wz1 * Bz1.y));
    float sz = wyr * (wx0 * fmaf(wz0, Az0z, wz1 * Az1z) +
                      wx1 * fmaf(wz0, Bz0z, wz1 * Bz1z));

    // Combine the two y rows across the lane pair.
    unsigned mask = __activemask();
    sx += __shfl_xor_sync(mask, sx, 1);
    sy += __shfl_xor_sync(mask, sy, 1);
    sz += __shfl_xor_sync(mask, sz, 1);

    if (r == 0) {
        __stcs(out + 3 * p + 0, sx);
        __stcs(out + 3 * p + 1, sy);
        __stcs(out + 3 * p + 2, sz);
    }
}

extern "C" void kernel_launch(void* const* d_in, const int* in_sizes, int n_in,
                              void* d_out, int out_size) {
    const float* coords = (const float*)d_in[0];   // (N_POINTS, 3) f32
    const float* theta  = (const float*)d_in[1];   // (160,160,160,3) f32
    float* out = (float*)d_out;                    // (N_POINTS, 3) f32

    int n = in_sizes[0] / 3;

    int repack_blocks = NX * (NY / TY);            // 160 * 8 = 1280
    repack_kernel<<<repack_blocks, 256>>>(theta);

    long long threads = 2LL * n;
    int blocks = (int)((threads + 255) / 256);
    trilerp_kernel<<<blocks, 256>>>(coords, out, n);
}